// round 3
// baseline (speedup 1.0000x reference)
#include <cuda_runtime.h>
#include <math.h>

// Problem constants (fixed by setup_inputs)
#define HW    65536          // 256*256
#define WIMG  256
#define CC    256
#define BB    2
#define NHH   16
#define DHH   16
#define TP    257            // pooled plane dim (H+1)
#define TPL   (TP*TP)

// ---------------- scratch (device globals; no allocs allowed) ----------------
static __device__ float g_q [BB*CC*HW];
static __device__ float g_k [BB*CC*HW];
static __device__ float g_v1[BB*CC*HW];
static __device__ float g_v2[BB*CC*HW];
static __device__ float g_o [BB*CC*HW];
static __device__ float g_t [BB*CC*TPL];
static __device__ float g_u [BB*CC*HW];
static __device__ float g_pwf[CC*CC];
static __device__ float g_pwb[CC];

// ---------------- prep: fold BN into pointwise weights ----------------
// pw'(o,c) = pw(o,c)*inv(c);  bias(o) = sum_c pw(o,c)*(beta(c)-mean(c)*inv(c))
__global__ void prep_kernel(const float* __restrict__ pw,
                            const float* __restrict__ gamma,
                            const float* __restrict__ beta,
                            const float* __restrict__ mean,
                            const float* __restrict__ var)
{
    __shared__ float red[256];
    int o = blockIdx.x, c = threadIdx.x;
    float inv = gamma[c] * rsqrtf(var[c] + 1e-5f);
    float w = pw[o*CC + c];
    g_pwf[o*CC + c] = w * inv;
    red[c] = w * (beta[c] - mean[c]*inv);
    __syncthreads();
    for (int s = 128; s > 0; s >>= 1) {
        if (c < s) red[c] += red[c+s];
        __syncthreads();
    }
    if (c == 0) g_pwb[o] = red[0];
}

// ---------------- qkv GEMM: out = W_sel @ X, X=[256,HW] channel-major ----------------
// which=0: x1 -> q (w rows 0..255), v1 (rows 512..767)
// which=1: x2 -> k (w rows 256..511), v2 (rows 512..767)
// grid (512, 4, B), block 256. 128x128 tile, BK=8, 8x8 per thread.
__global__ void __launch_bounds__(256) qkv_gemm(const float* __restrict__ X,
                                                const float* __restrict__ Wq,
                                                int which)
{
    int b  = blockIdx.z;
    int by = blockIdx.y;
    int n0 = blockIdx.x * 128;
    float* outA = which ? g_k  : g_q;
    float* outB = which ? g_v2 : g_v1;
    int wrowA   = which ? 256 : 0;
    const float* wb;
    float* ob;
    if (by < 2) { wb = Wq + (size_t)(wrowA + by*128)*CC;
                  ob = outA + (size_t)b*CC*HW + (size_t)(by*128)*HW; }
    else        { wb = Wq + (size_t)(512 + (by-2)*128)*CC;
                  ob = outB + (size_t)b*CC*HW + (size_t)((by-2)*128)*HW; }
    const float* xb = X + (size_t)b*CC*HW;

    __shared__ __align__(16) float As[8][128];
    __shared__ __align__(16) float Bs[8][128];

    int tid  = threadIdx.x;
    int arow = tid >> 1,  acol = (tid & 1)  * 4;
    int brow = tid >> 5,  bcol = (tid & 31) * 4;
    int ty   = tid >> 4,  tx   = tid & 15;

    float acc[8][8];
    #pragma unroll
    for (int i = 0; i < 8; i++)
        #pragma unroll
        for (int j = 0; j < 8; j++) acc[i][j] = 0.f;

    for (int k0 = 0; k0 < CC; k0 += 8) {
        float4 avr = *(const float4*)(wb + arow*CC + k0 + acol);
        float4 bvr = *(const float4*)(xb + (size_t)(k0 + brow)*HW + n0 + bcol);
        __syncthreads();
        As[acol+0][arow] = avr.x;
        As[acol+1][arow] = avr.y;
        As[acol+2][arow] = avr.z;
        As[acol+3][arow] = avr.w;
        *(float4*)&Bs[brow][bcol] = bvr;
        __syncthreads();
        #pragma unroll
        for (int k = 0; k < 8; k++) {
            float4 a0 = *(const float4*)&As[k][ty*8];
            float4 a1 = *(const float4*)&As[k][ty*8+4];
            float4 b0 = *(const float4*)&Bs[k][tx*8];
            float4 b1 = *(const float4*)&Bs[k][tx*8+4];
            float ar[8] = {a0.x,a0.y,a0.z,a0.w,a1.x,a1.y,a1.z,a1.w};
            float br[8] = {b0.x,b0.y,b0.z,b0.w,b1.x,b1.y,b1.z,b1.w};
            #pragma unroll
            for (int i = 0; i < 8; i++)
                #pragma unroll
                for (int j = 0; j < 8; j++)
                    acc[i][j] += ar[i]*br[j];
        }
    }
    #pragma unroll
    for (int i = 0; i < 8; i++) {
        int row = ty*8 + i;
        float* op = ob + (size_t)row*HW + n0 + tx*8;
        *(float4*)op     = make_float4(acc[i][0],acc[i][1],acc[i][2],acc[i][3]);
        *(float4*)(op+4) = make_float4(acc[i][4],acc[i][5],acc[i][6],acc[i][7]);
    }
}

// ---------------- window attention: one block per (window, head) ----------------
// o = 0.5*( softmax(q k^T * 0.25 + bias) @ (v1-v2) + sum_k v2 )
__global__ void __launch_bounds__(128) attn_kernel(const float* __restrict__ rel_bias)
{
    int wid = blockIdx.x;                 // 0..2047
    int h   = blockIdx.y;                 // 0..15
    int b   = wid >> 10;
    int wy  = (wid >> 5) & 31;
    int wx  = wid & 31;
    int tid = threadIdx.x;

    __shared__ __align__(16) float sq [16][64];   // [d][token]
    __shared__ __align__(16) float sk [16][64];
    __shared__ __align__(16) float svd[64][16];   // v1-v2, [token][d]
    __shared__ __align__(16) float sv2[64][16];
    __shared__ float ss[64][65];                  // scores -> probs (padded)
    __shared__ float sbias[232];
    __shared__ float spart[8][16];
    __shared__ float svsum[16];

    size_t base = ((size_t)b*CC + h*DHH)*HW + (size_t)(wy*8)*WIMG + wx*8;

    for (int e = tid; e < 1024; e += 128) {
        int dd = e >> 6, t = e & 63;
        int ty = t >> 3, tx = t & 7;
        size_t g = base + (size_t)dd*HW + (size_t)ty*WIMG + tx;
        sq[dd][t] = g_q[g];
        sk[dd][t] = g_k[g];
        float a = g_v1[g], bb2 = g_v2[g];
        svd[t][dd] = a - bb2;
        sv2[t][dd] = bb2;
    }
    for (int e = tid; e < 225; e += 128) sbias[e] = rel_bias[e*NHH + h];
    __syncthreads();

    // sum_j v2[j][d]
    {
        int pd = tid & 15, pp = tid >> 4;
        float s = 0.f;
        #pragma unroll
        for (int t = 0; t < 8; t++) s += sv2[pp*8 + t][pd];
        spart[pp][pd] = s;
    }
    __syncthreads();
    if (tid < 16) {
        float s = 0.f;
        #pragma unroll
        for (int p = 0; p < 8; p++) s += spart[p][tid];
        svsum[tid] = s;
    }

    // scores: thread computes 4x8 tile of 64x64
    int ti = tid >> 3, tj = tid & 7;
    int i0 = ti*4, j0 = tj*8;
    float acc[4][8];
    #pragma unroll
    for (int a = 0; a < 4; a++)
        #pragma unroll
        for (int j = 0; j < 8; j++) acc[a][j] = 0.f;

    #pragma unroll
    for (int dd = 0; dd < 16; dd++) {
        float4 qa  = *(const float4*)&sq[dd][i0];
        float4 kb0 = *(const float4*)&sk[dd][j0];
        float4 kb1 = *(const float4*)&sk[dd][j0+4];
        float qv[4] = {qa.x,qa.y,qa.z,qa.w};
        float kv[8] = {kb0.x,kb0.y,kb0.z,kb0.w,kb1.x,kb1.y,kb1.z,kb1.w};
        #pragma unroll
        for (int a = 0; a < 4; a++)
            #pragma unroll
            for (int j = 0; j < 8; j++)
                acc[a][j] += qv[a]*kv[j];
    }
    #pragma unroll
    for (int a = 0; a < 4; a++) {
        int i = i0 + a, yi = i >> 3, xi = i & 7;
        #pragma unroll
        for (int j = 0; j < 8; j++) {
            int jj = j0 + j, yj = jj >> 3, xj = jj & 7;
            int idx = (yi - yj + 7)*15 + (xi - xj + 7);
            ss[i][jj] = acc[a][j]*0.25f + sbias[idx];
        }
    }
    __syncthreads();

    // softmax: 4 warps x 16 rows
    int warp = tid >> 5, lane = tid & 31;
    for (int r = warp*16; r < warp*16 + 16; r++) {
        float v0 = ss[r][lane], v1 = ss[r][lane+32];
        float m = fmaxf(v0, v1);
        #pragma unroll
        for (int o = 16; o > 0; o >>= 1) m = fmaxf(m, __shfl_xor_sync(0xffffffffu, m, o));
        float e0 = __expf(v0 - m), e1 = __expf(v1 - m);
        float s = e0 + e1;
        #pragma unroll
        for (int o = 16; o > 0; o >>= 1) s += __shfl_xor_sync(0xffffffffu, s, o);
        float inv = 1.0f / s;
        ss[r][lane]    = e0*inv;
        ss[r][lane+32] = e1*inv;
    }
    __syncthreads();

    // AV: thread owns one query row i, 8 of 16 d-channels
    int qi  = tid >> 1;
    int dd0 = (tid & 1)*8;
    float av[8];
    #pragma unroll
    for (int d = 0; d < 8; d++) av[d] = 0.f;
    const float* srow = &ss[qi][0];
    #pragma unroll 4
    for (int j = 0; j < 64; j++) {
        float a = srow[j];
        float4 v0 = *(const float4*)&svd[j][dd0];
        float4 v1 = *(const float4*)&svd[j][dd0+4];
        av[0] += a*v0.x; av[1] += a*v0.y; av[2] += a*v0.z; av[3] += a*v0.w;
        av[4] += a*v1.x; av[5] += a*v1.y; av[6] += a*v1.z; av[7] += a*v1.w;
    }
    int ty = qi >> 3, tx = qi & 7;
    size_t og = base + (size_t)dd0*HW + (size_t)ty*WIMG + tx;
    #pragma unroll
    for (int d = 0; d < 8; d++)
        g_o[og + (size_t)d*HW] = 0.5f*(av[d] + svsum[dd0 + d]);
}

// ---------------- directional avg pools + pad_out ----------------
// t[y][x] = (sum_{r=y-3..y+4} oP[r][x] + sum_{c=x-3..x+4} oQ[y][c]) / 8
// oP/oQ reflect the last row/col (index 256 -> 254), zero outside [0,256].
// t row 256 and col 256 are zero (pad_out).
__global__ void pool_kernel()
{
    int p = blockIdx.x*256 + threadIdx.x;
    if (p >= TPL) return;
    int c = blockIdx.y, b = blockIdx.z;
    int y = p / TP, x = p - y*TP;
    const float* ob = g_o + ((size_t)b*CC + c)*HW;
    float val = 0.f;
    if (y < 256 && x < 256) {
        float sx = 0.f, sy = 0.f;
        #pragma unroll
        for (int t = 0; t < 8; t++) {
            int r = y - 3 + t;
            if (r >= 0 && r <= 256) sx += ob[(r == 256 ? 254 : r)*WIMG + x];
            int cl = x - 3 + t;
            if (cl >= 0 && cl <= 256) sy += ob[y*WIMG + (cl == 256 ? 254 : cl)];
        }
        val = (sx + sy)*0.125f;
    }
    g_t[((size_t)b*CC + c)*TPL + p] = val;
}

// ---------------- depthwise 8x8 conv (pad 3) over t[257x257] -> u[256x256] ----------------
__global__ void __launch_bounds__(256) dw_kernel(const float* __restrict__ dw)
{
    __shared__ float st[39][41];
    __shared__ float sdw[64];
    int bc = blockIdx.z;                       // b*256 + c
    int y0 = blockIdx.y*32, x0 = blockIdx.x*32;
    const float* tb = g_t + (size_t)bc*TPL;
    int tid = threadIdx.x;
    if (tid < 64) sdw[tid] = dw[(bc & 255)*64 + tid];
    for (int idx = tid; idx < 39*39; idx += 256) {
        int r = idx / 39, cl = idx - r*39;
        int gy = y0 - 3 + r, gx = x0 - 3 + cl;
        float v = 0.f;
        if (gy >= 0 && gy < TP && gx >= 0 && gx < TP) v = tb[gy*TP + gx];
        st[r][cl] = v;
    }
    __syncthreads();
    int oy = tid >> 3, ox = (tid & 7)*4;
    float a0 = 0.f, a1 = 0.f, a2 = 0.f, a3 = 0.f;
    #pragma unroll
    for (int ky = 0; ky < 8; ky++) {
        const float* row = &st[oy+ky][ox];
        #pragma unroll
        for (int kx = 0; kx < 8; kx++) {
            float wv = sdw[ky*8 + kx];
            a0 += wv*row[kx];
            a1 += wv*row[kx+1];
            a2 += wv*row[kx+2];
            a3 += wv*row[kx+3];
        }
    }
    float* up = g_u + (size_t)bc*HW + (size_t)(y0+oy)*WIMG + x0 + ox;
    *(float4*)up = make_float4(a0,a1,a2,a3);
}

// ---------------- pointwise GEMM (BN folded) + bias ----------------
__global__ void __launch_bounds__(256) pw_gemm(float* __restrict__ out)
{
    int b  = blockIdx.z;
    int by = blockIdx.y;                      // 0..1
    int n0 = blockIdx.x * 128;
    const float* wb = g_pwf + (size_t)(by*128)*CC;
    const float* xb = g_u + (size_t)b*CC*HW;
    float* ob = out + (size_t)b*CC*HW + (size_t)(by*128)*HW;

    __shared__ __align__(16) float As[8][128];
    __shared__ __align__(16) float Bs[8][128];

    int tid  = threadIdx.x;
    int arow = tid >> 1,  acol = (tid & 1)  * 4;
    int brow = tid >> 5,  bcol = (tid & 31) * 4;
    int ty   = tid >> 4,  tx   = tid & 15;

    float acc[8][8];
    #pragma unroll
    for (int i = 0; i < 8; i++)
        #pragma unroll
        for (int j = 0; j < 8; j++) acc[i][j] = 0.f;

    for (int k0 = 0; k0 < CC; k0 += 8) {
        float4 avr = *(const float4*)(wb + arow*CC + k0 + acol);
        float4 bvr = *(const float4*)(xb + (size_t)(k0 + brow)*HW + n0 + bcol);
        __syncthreads();
        As[acol+0][arow] = avr.x;
        As[acol+1][arow] = avr.y;
        As[acol+2][arow] = avr.z;
        As[acol+3][arow] = avr.w;
        *(float4*)&Bs[brow][bcol] = bvr;
        __syncthreads();
        #pragma unroll
        for (int k = 0; k < 8; k++) {
            float4 a0 = *(const float4*)&As[k][ty*8];
            float4 a1 = *(const float4*)&As[k][ty*8+4];
            float4 b0 = *(const float4*)&Bs[k][tx*8];
            float4 b1 = *(const float4*)&Bs[k][tx*8+4];
            float ar[8] = {a0.x,a0.y,a0.z,a0.w,a1.x,a1.y,a1.z,a1.w};
            float br[8] = {b0.x,b0.y,b0.z,b0.w,b1.x,b1.y,b1.z,b1.w};
            #pragma unroll
            for (int i = 0; i < 8; i++)
                #pragma unroll
                for (int j = 0; j < 8; j++)
                    acc[i][j] += ar[i]*br[j];
        }
    }
    #pragma unroll
    for (int i = 0; i < 8; i++) {
        int row = ty*8 + i;
        float bias = g_pwb[by*128 + row];
        float* op = ob + (size_t)row*HW + n0 + tx*8;
        *(float4*)op     = make_float4(acc[i][0]+bias, acc[i][1]+bias,
                                       acc[i][2]+bias, acc[i][3]+bias);
        *(float4*)(op+4) = make_float4(acc[i][4]+bias, acc[i][5]+bias,
                                       acc[i][6]+bias, acc[i][7]+bias);
    }
}

// ---------------- launch ----------------
extern "C" void kernel_launch(void* const* d_in, const int* in_sizes, int n_in,
                              void* d_out, int out_size)
{
    const float* x1       = (const float*)d_in[0];
    const float* x2       = (const float*)d_in[1];
    const float* qkv_w    = (const float*)d_in[2];
    const float* rel_bias = (const float*)d_in[3];
    const float* dw_w     = (const float*)d_in[4];
    const float* bn_g     = (const float*)d_in[5];
    const float* bn_b     = (const float*)d_in[6];
    const float* bn_m     = (const float*)d_in[7];
    const float* bn_v     = (const float*)d_in[8];
    const float* pw_w     = (const float*)d_in[9];
    float* out = (float*)d_out;

    prep_kernel<<<256, 256>>>(pw_w, bn_g, bn_b, bn_m, bn_v);
    qkv_gemm<<<dim3(512, 4, BB), 256>>>(x1, qkv_w, 0);
    qkv_gemm<<<dim3(512, 4, BB), 256>>>(x2, qkv_w, 1);
    attn_kernel<<<dim3(2048, NHH), 128>>>(rel_bias);
    pool_kernel<<<dim3((TPL + 255)/256, CC, BB), 256>>>();
    dw_kernel<<<dim3(8, 8, BB*CC), 256>>>(dw_w);
    pw_gemm<<<dim3(512, 2, BB), 256>>>(out);
}

// round 4
// speedup vs baseline: 1.6973x; 1.6973x over previous
#include <cuda_runtime.h>
#include <math.h>

// Problem constants (fixed by setup_inputs)
#define HW    65536          // 256*256
#define WIMG  256
#define CC    256
#define BB    2
#define NHH   16
#define DHH   16
#define TP    257            // pooled plane dim (H+1)
#define TPL   (TP*TP)

// ---------------- scratch (device globals; no allocs allowed) ----------------
static __device__ float g_q [BB*CC*HW];
static __device__ float g_k [BB*CC*HW];
static __device__ float g_v1[BB*CC*HW];
static __device__ float g_v2[BB*CC*HW];
static __device__ float g_o [BB*CC*HW];
static __device__ float g_t [BB*CC*TPL];
static __device__ float g_u [BB*CC*HW];
static __device__ float g_pwf[CC*CC];
static __device__ float g_pwb[CC];

// ---------------- prep: fold BN into pointwise weights ----------------
__global__ void prep_kernel(const float* __restrict__ pw,
                            const float* __restrict__ gamma,
                            const float* __restrict__ beta,
                            const float* __restrict__ mean,
                            const float* __restrict__ var)
{
    __shared__ float red[256];
    int o = blockIdx.x, c = threadIdx.x;
    float inv = gamma[c] * rsqrtf(var[c] + 1e-5f);
    float w = pw[o*CC + c];
    g_pwf[o*CC + c] = w * inv;
    red[c] = w * (beta[c] - mean[c]*inv);
    __syncthreads();
    for (int s = 128; s > 0; s >>= 1) {
        if (c < s) red[c] += red[c+s];
        __syncthreads();
    }
    if (c == 0) g_pwb[o] = red[0];
}

// ---------------- tf32 helpers ----------------
__device__ __forceinline__ unsigned f2tf(float x) {
    unsigned r; asm("cvt.rna.tf32.f32 %0, %1;" : "=r"(r) : "f"(x)); return r;
}

__device__ __forceinline__ void mma8(float* c, const unsigned* a, const unsigned* b) {
    asm volatile(
        "mma.sync.aligned.m16n8k8.row.col.f32.tf32.tf32.f32 "
        "{%0,%1,%2,%3},{%4,%5,%6,%7},{%8,%9},{%0,%1,%2,%3};"
        : "+f"(c[0]), "+f"(c[1]), "+f"(c[2]), "+f"(c[3])
        : "r"(a[0]), "r"(a[1]), "r"(a[2]), "r"(a[3]), "r"(b[0]), "r"(b[1]));
}

// ---------------- core tf32 GEMM tile: 128(M) x 128(N), K=256 ----------------
// wb: [128, 256] row-major weights. xb: [256, HW] activations (batch base).
// ob: output base (row*HW + n0 + col). bias: per-row (128) or nullptr.
// block = 256 threads = 8 warps (4m x 2n), warp tile 32x64, mma m16n8k8.
#define SA 136   // padded smem row stride (words); tig*8+gid conflict-free

__device__ __forceinline__ void gemm128_tf32(
    const float* __restrict__ wb,
    const float* __restrict__ xb,
    float* __restrict__ ob,
    int n0,
    const float* __restrict__ bias)
{
    __shared__ __align__(16) unsigned As[16*SA];
    __shared__ __align__(16) unsigned Bs[16*SA];

    int tid  = threadIdx.x;
    int lane = tid & 31, warp = tid >> 5;
    int wm = warp >> 1, wn = warp & 1;
    int gid = lane >> 2, tig = lane & 3;

    float acc[2][8][4];
    #pragma unroll
    for (int mt = 0; mt < 2; mt++)
        #pragma unroll
        for (int nt = 0; nt < 8; nt++)
            #pragma unroll
            for (int i = 0; i < 4; i++) acc[mt][nt][i] = 0.f;

    int arow = tid >> 1,  akq = (tid & 1) * 8;   // A: 128 rows x 16 k
    int brow = tid >> 4,  bnq = (tid & 15) * 8;  // B: 16 k x 128 n

    for (int k0 = 0; k0 < CC; k0 += 16) {
        float4 a0 = *(const float4*)(wb + (size_t)arow*CC + k0 + akq);
        float4 a1 = *(const float4*)(wb + (size_t)arow*CC + k0 + akq + 4);
        float4 b0 = *(const float4*)(xb + (size_t)(k0 + brow)*HW + n0 + bnq);
        float4 b1 = *(const float4*)(xb + (size_t)(k0 + brow)*HW + n0 + bnq + 4);
        __syncthreads();
        As[(akq+0)*SA + arow] = f2tf(a0.x);
        As[(akq+1)*SA + arow] = f2tf(a0.y);
        As[(akq+2)*SA + arow] = f2tf(a0.z);
        As[(akq+3)*SA + arow] = f2tf(a0.w);
        As[(akq+4)*SA + arow] = f2tf(a1.x);
        As[(akq+5)*SA + arow] = f2tf(a1.y);
        As[(akq+6)*SA + arow] = f2tf(a1.z);
        As[(akq+7)*SA + arow] = f2tf(a1.w);
        *(uint4*)&Bs[brow*SA + bnq]     = make_uint4(f2tf(b0.x), f2tf(b0.y), f2tf(b0.z), f2tf(b0.w));
        *(uint4*)&Bs[brow*SA + bnq + 4] = make_uint4(f2tf(b1.x), f2tf(b1.y), f2tf(b1.z), f2tf(b1.w));
        __syncthreads();

        #pragma unroll
        for (int kk = 0; kk < 16; kk += 8) {
            unsigned af[2][4], bf[8][2];
            #pragma unroll
            for (int mt = 0; mt < 2; mt++) {
                int m = wm*32 + mt*16 + gid;
                af[mt][0] = As[(kk+tig  )*SA + m];
                af[mt][1] = As[(kk+tig  )*SA + m + 8];
                af[mt][2] = As[(kk+tig+4)*SA + m];
                af[mt][3] = As[(kk+tig+4)*SA + m + 8];
            }
            #pragma unroll
            for (int nt = 0; nt < 8; nt++) {
                int n = wn*64 + nt*8 + gid;
                bf[nt][0] = Bs[(kk+tig  )*SA + n];
                bf[nt][1] = Bs[(kk+tig+4)*SA + n];
            }
            #pragma unroll
            for (int mt = 0; mt < 2; mt++)
                #pragma unroll
                for (int nt = 0; nt < 8; nt++)
                    mma8(acc[mt][nt], af[mt], bf[nt]);
        }
    }

    #pragma unroll
    for (int mt = 0; mt < 2; mt++) {
        int r0 = wm*32 + mt*16 + gid;
        float bia0 = bias ? bias[r0]     : 0.f;
        float bia1 = bias ? bias[r0 + 8] : 0.f;
        #pragma unroll
        for (int nt = 0; nt < 8; nt++) {
            int c = n0 + wn*64 + nt*8 + 2*tig;
            *(float2*)(ob + (size_t)r0*HW + c) =
                make_float2(acc[mt][nt][0] + bia0, acc[mt][nt][1] + bia0);
            *(float2*)(ob + (size_t)(r0+8)*HW + c) =
                make_float2(acc[mt][nt][2] + bia1, acc[mt][nt][3] + bia1);
        }
    }
}

// ---------------- qkv GEMM (tf32 tensor cores) ----------------
// which=0: x1 -> q (W rows 0..255), v1 (rows 512..767)
// which=1: x2 -> k (W rows 256..511), v2 (rows 512..767)
__global__ void __launch_bounds__(256) qkv_gemm(const float* __restrict__ X,
                                                const float* __restrict__ Wq,
                                                int which)
{
    int b  = blockIdx.z;
    int by = blockIdx.y;
    int n0 = blockIdx.x * 128;
    float* outA = which ? g_k  : g_q;
    float* outB = which ? g_v2 : g_v1;
    int wrowA   = which ? 256 : 0;
    const float* wb;
    float* ob;
    if (by < 2) { wb = Wq + (size_t)(wrowA + by*128)*CC;
                  ob = outA + (size_t)b*CC*HW + (size_t)(by*128)*HW; }
    else        { wb = Wq + (size_t)(512 + (by-2)*128)*CC;
                  ob = outB + (size_t)b*CC*HW + (size_t)((by-2)*128)*HW; }
    const float* xb = X + (size_t)b*CC*HW;
    gemm128_tf32(wb, xb, ob, n0, nullptr);
}

// ---------------- pointwise GEMM (BN folded, tf32) ----------------
__global__ void __launch_bounds__(256) pw_gemm(float* __restrict__ out)
{
    int b  = blockIdx.z;
    int by = blockIdx.y;                      // 0..1
    int n0 = blockIdx.x * 128;
    const float* wb = g_pwf + (size_t)(by*128)*CC;
    const float* xb = g_u + (size_t)b*CC*HW;
    float* ob = out + (size_t)b*CC*HW + (size_t)(by*128)*HW;
    gemm128_tf32(wb, xb, ob, n0, g_pwb + by*128);
}

// ---------------- window attention: register-resident ----------------
// o = 0.5*( softmax(q k^T * 0.25 + bias) @ (v1-v2) + sum_k v2 )
// 128 threads: thread owns query row qi = tid>>1, key half jh = tid&1 (32 keys).
#define SV 20   // padded token-major stride

__global__ void __launch_bounds__(128) attn_kernel(const float* __restrict__ rel_bias)
{
    int wid = blockIdx.x;                 // 0..2047
    int h   = blockIdx.y;                 // 0..15
    int b   = wid >> 10;
    int wy  = (wid >> 5) & 31;
    int wx  = wid & 31;
    int tid = threadIdx.x;

    __shared__ __align__(16) float sq [64*SV];   // [token][d]
    __shared__ __align__(16) float sk [64*SV];
    __shared__ __align__(16) float svd[64*SV];   // v1-v2
    __shared__ __align__(16) float sv2[64*SV];
    __shared__ float sbias[240];

    size_t base = ((size_t)b*CC + h*DHH)*HW + (size_t)(wy*8)*WIMG + wx*8;

    for (int e = tid; e < 1024; e += 128) {
        int dd = e >> 6, t = e & 63;
        int ty = t >> 3, tx = t & 7;
        size_t g = base + (size_t)dd*HW + (size_t)ty*WIMG + tx;
        sq[t*SV + dd] = g_q[g];
        sk[t*SV + dd] = g_k[g];
        float a = g_v1[g], c2 = g_v2[g];
        svd[t*SV + dd] = a - c2;
        sv2[t*SV + dd] = c2;
    }
    for (int e = tid; e < 225; e += 128) sbias[e] = rel_bias[e*NHH + h];
    __syncthreads();

    int qi = tid >> 1, jh = tid & 1;
    int yi = qi >> 3, xi = qi & 7;
    int j0 = jh * 32;

    // q row into registers
    float qr[16];
    #pragma unroll
    for (int d4 = 0; d4 < 16; d4 += 4) {
        float4 v = *(const float4*)&sq[qi*SV + d4];
        qr[d4] = v.x; qr[d4+1] = v.y; qr[d4+2] = v.z; qr[d4+3] = v.w;
    }

    // scores for my 32 keys
    float sc[32];
    #pragma unroll
    for (int jj = 0; jj < 32; jj++) {
        int j = j0 + jj;
        float4 k0 = *(const float4*)&sk[j*SV + 0];
        float4 k1 = *(const float4*)&sk[j*SV + 4];
        float4 k2 = *(const float4*)&sk[j*SV + 8];
        float4 k3 = *(const float4*)&sk[j*SV + 12];
        float s =
            qr[0]*k0.x + qr[1]*k0.y + qr[2]*k0.z + qr[3]*k0.w +
            qr[4]*k1.x + qr[5]*k1.y + qr[6]*k1.z + qr[7]*k1.w +
            qr[8]*k2.x + qr[9]*k2.y + qr[10]*k2.z + qr[11]*k2.w +
            qr[12]*k3.x + qr[13]*k3.y + qr[14]*k3.z + qr[15]*k3.w;
        int yj = j >> 3, xj = j & 7;
        sc[jj] = s*0.25f + sbias[(yi - yj + 7)*15 + (xi - xj + 7)];
    }

    // softmax across 64 keys (pairwise with partner thread tid^1)
    float m = sc[0];
    #pragma unroll
    for (int jj = 1; jj < 32; jj++) m = fmaxf(m, sc[jj]);
    m = fmaxf(m, __shfl_xor_sync(0xffffffffu, m, 1));
    float sum = 0.f;
    #pragma unroll
    for (int jj = 0; jj < 32; jj++) { sc[jj] = __expf(sc[jj] - m); sum += sc[jj]; }
    sum += __shfl_xor_sync(0xffffffffu, sum, 1);
    float inv = 1.0f / sum;
    #pragma unroll
    for (int jj = 0; jj < 32; jj++) sc[jj] *= inv;

    // AV over my half: acc[d] = sum_j ( p_j*(v1-v2)[j][d] + v2[j][d] )
    float acc[16];
    #pragma unroll
    for (int d = 0; d < 16; d++) acc[d] = 0.f;
    #pragma unroll
    for (int jj = 0; jj < 32; jj++) {
        int j = j0 + jj;
        float p = sc[jj];
        float4 a0 = *(const float4*)&svd[j*SV + 0];
        float4 a1 = *(const float4*)&svd[j*SV + 4];
        float4 a2 = *(const float4*)&svd[j*SV + 8];
        float4 a3 = *(const float4*)&svd[j*SV + 12];
        float4 c0 = *(const float4*)&sv2[j*SV + 0];
        float4 c1 = *(const float4*)&sv2[j*SV + 4];
        float4 c2 = *(const float4*)&sv2[j*SV + 8];
        float4 c3 = *(const float4*)&sv2[j*SV + 12];
        acc[0]  += p*a0.x + c0.x;  acc[1]  += p*a0.y + c0.y;
        acc[2]  += p*a0.z + c0.z;  acc[3]  += p*a0.w + c0.w;
        acc[4]  += p*a1.x + c1.x;  acc[5]  += p*a1.y + c1.y;
        acc[6]  += p*a1.z + c1.z;  acc[7]  += p*a1.w + c1.w;
        acc[8]  += p*a2.x + c2.x;  acc[9]  += p*a2.y + c2.y;
        acc[10] += p*a2.z + c2.z;  acc[11] += p*a2.w + c2.w;
        acc[12] += p*a3.x + c3.x;  acc[13] += p*a3.y + c3.y;
        acc[14] += p*a3.z + c3.z;  acc[15] += p*a3.w + c3.w;
    }
    // combine halves
    #pragma unroll
    for (int d = 0; d < 16; d++)
        acc[d] += __shfl_xor_sync(0xffffffffu, acc[d], 1);

    // write: even thread writes d 0..7, odd writes d 8..15
    int d0 = jh * 8;
    size_t og = base + (size_t)yi*WIMG + xi;
    #pragma unroll
    for (int d = 0; d < 8; d++)
        g_o[og + (size_t)(d0 + d)*HW] = 0.5f*acc[d0 + d];
}

// ---------------- directional avg pools + pad_out ----------------
__global__ void pool_kernel()
{
    int p = blockIdx.x*256 + threadIdx.x;
    if (p >= TPL) return;
    int c = blockIdx.y, b = blockIdx.z;
    int y = p / TP, x = p - y*TP;
    const float* ob = g_o + ((size_t)b*CC + c)*HW;
    float val = 0.f;
    if (y < 256 && x < 256) {
        float sx = 0.f, sy = 0.f;
        #pragma unroll
        for (int t = 0; t < 8; t++) {
            int r = y - 3 + t;
            if (r >= 0 && r <= 256) sx += ob[(r == 256 ? 254 : r)*WIMG + x];
            int cl = x - 3 + t;
            if (cl >= 0 && cl <= 256) sy += ob[y*WIMG + (cl == 256 ? 254 : cl)];
        }
        val = (sx + sy)*0.125f;
    }
    g_t[((size_t)b*CC + c)*TPL + p] = val;
}

// ---------------- depthwise 8x8 conv (pad 3) over t[257x257] -> u[256x256] ----------------
__global__ void __launch_bounds__(256) dw_kernel(const float* __restrict__ dw)
{
    __shared__ float st[39][41];
    __shared__ float sdw[64];
    int bc = blockIdx.z;                       // b*256 + c
    int y0 = blockIdx.y*32, x0 = blockIdx.x*32;
    const float* tb = g_t + (size_t)bc*TPL;
    int tid = threadIdx.x;
    if (tid < 64) sdw[tid] = dw[(bc & 255)*64 + tid];
    for (int idx = tid; idx < 39*39; idx += 256) {
        int r = idx / 39, cl = idx - r*39;
        int gy = y0 - 3 + r, gx = x0 - 3 + cl;
        float v = 0.f;
        if (gy >= 0 && gy < TP && gx >= 0 && gx < TP) v = tb[gy*TP + gx];
        st[r][cl] = v;
    }
    __syncthreads();
    int oy = tid >> 3, ox = (tid & 7)*4;
    float a0 = 0.f, a1 = 0.f, a2 = 0.f, a3 = 0.f;
    #pragma unroll
    for (int ky = 0; ky < 8; ky++) {
        const float* row = &st[oy+ky][ox];
        #pragma unroll
        for (int kx = 0; kx < 8; kx++) {
            float wv = sdw[ky*8 + kx];
            a0 += wv*row[kx];
            a1 += wv*row[kx+1];
            a2 += wv*row[kx+2];
            a3 += wv*row[kx+3];
        }
    }
    float* up = g_u + (size_t)bc*HW + (size_t)(y0+oy)*WIMG + x0 + ox;
    *(float4*)up = make_float4(a0,a1,a2,a3);
}

// ---------------- launch ----------------
extern "C" void kernel_launch(void* const* d_in, const int* in_sizes, int n_in,
                              void* d_out, int out_size)
{
    const float* x1       = (const float*)d_in[0];
    const float* x2       = (const float*)d_in[1];
    const float* qkv_w    = (const float*)d_in[2];
    const float* rel_bias = (const float*)d_in[3];
    const float* dw_w     = (const float*)d_in[4];
    const float* bn_g     = (const float*)d_in[5];
    const float* bn_b     = (const float*)d_in[6];
    const float* bn_m     = (const float*)d_in[7];
    const float* bn_v     = (const float*)d_in[8];
    const float* pw_w     = (const float*)d_in[9];
    float* out = (float*)d_out;

    prep_kernel<<<256, 256>>>(pw_w, bn_g, bn_b, bn_m, bn_v);
    qkv_gemm<<<dim3(512, 4, BB), 256>>>(x1, qkv_w, 0);
    qkv_gemm<<<dim3(512, 4, BB), 256>>>(x2, qkv_w, 1);
    attn_kernel<<<dim3(2048, NHH), 128>>>(rel_bias);
    pool_kernel<<<dim3((TPL + 255)/256, CC, BB), 256>>>();
    dw_kernel<<<dim3(8, 8, BB*CC), 256>>>(dw_w);
    pw_gemm<<<dim3(512, 2, BB), 256>>>(out);
}

// round 5
// speedup vs baseline: 2.1004x; 1.2375x over previous
#include <cuda_runtime.h>
#include <math.h>

// Problem constants (fixed by setup_inputs)
#define HW    65536          // 256*256
#define WIMG  256
#define CC    256
#define BB    2
#define NHH   16
#define DHH   16
#define TP    257            // pooled plane dim (H+1)
#define TPL   (TP*TP)

#define QSCALE 0.3606737602222409f    // 0.25 * log2(e)
#define LOG2E  1.4426950408889634f

// ---------------- scratch (device globals; no allocs allowed) ----------------
static __device__ float g_q [BB*CC*HW];
static __device__ float g_k [BB*CC*HW];
static __device__ float g_v1[BB*CC*HW];
static __device__ float g_v2[BB*CC*HW];
static __device__ float g_o [BB*CC*HW];
static __device__ float g_t [BB*CC*TPL];
static __device__ float g_u [BB*CC*HW];
static __device__ float g_pwf[CC*CC];
static __device__ float g_pwb[CC];
static __device__ float g_biasf[NHH*4*8*128*4];   // bias in mma C-fragment layout

// ---------------- prep: fold BN into pointwise weights ----------------
__global__ void prep_kernel(const float* __restrict__ pw,
                            const float* __restrict__ gamma,
                            const float* __restrict__ beta,
                            const float* __restrict__ mean,
                            const float* __restrict__ var)
{
    __shared__ float red[256];
    int o = blockIdx.x, c = threadIdx.x;
    float inv = gamma[c] * rsqrtf(var[c] + 1e-5f);
    float w = pw[o*CC + c];
    g_pwf[o*CC + c] = w * inv;
    red[c] = w * (beta[c] - mean[c]*inv);
    __syncthreads();
    for (int s = 128; s > 0; s >>= 1) {
        if (c < s) red[c] += red[c+s];
        __syncthreads();
    }
    if (c == 0) g_pwb[o] = red[0];
}

// ---------------- bias prep: rel-pos bias in mma C-fragment layout, x log2e ----
// layout: g_biasf[((h*4 + mi)*8 + ni)*128 + lane*4 + {c0,c1,c2,c3}]
__global__ void bias_prep(const float* __restrict__ rel_bias)
{
    int h = blockIdx.x, mi = blockIdx.y, ni = blockIdx.z;
    int lane = threadIdx.x;
    int g = lane >> 2, t = lane & 3;
    float v[4];
    #pragma unroll
    for (int rr = 0; rr < 2; rr++) {
        int i = mi*16 + g + rr*8;
        #pragma unroll
        for (int cc = 0; cc < 2; cc++) {
            int j = ni*8 + 2*t + cc;
            int idx = ((i>>3) - (j>>3) + 7)*15 + ((i&7) - (j&7) + 7);
            v[rr*2 + cc] = LOG2E * rel_bias[idx*NHH + h];
        }
    }
    *(float4*)&g_biasf[(((h*4 + mi)*8 + ni)*128 + lane*4)] =
        make_float4(v[0], v[1], v[2], v[3]);
}

// ---------------- tf32 helpers ----------------
__device__ __forceinline__ unsigned f2tf(float x) {
    unsigned r; asm("cvt.rna.tf32.f32 %0, %1;" : "=r"(r) : "f"(x)); return r;
}
__device__ __forceinline__ float ex2(float x) {
    float r; asm("ex2.approx.ftz.f32 %0, %1;" : "=f"(r) : "f"(x)); return r;
}
__device__ __forceinline__ void mma8(float* c, const unsigned* a, const unsigned* b) {
    asm volatile(
        "mma.sync.aligned.m16n8k8.row.col.f32.tf32.tf32.f32 "
        "{%0,%1,%2,%3},{%4,%5,%6,%7},{%8,%9},{%0,%1,%2,%3};"
        : "+f"(c[0]), "+f"(c[1]), "+f"(c[2]), "+f"(c[3])
        : "r"(a[0]), "r"(a[1]), "r"(a[2]), "r"(a[3]), "r"(b[0]), "r"(b[1]));
}

// ---------------- core tf32 GEMM tile: 128(M) x 128(N), K=256 ----------------
#define SA 136

__device__ __forceinline__ void gemm128_tf32(
    const float* __restrict__ wb,
    const float* __restrict__ xb,
    float* __restrict__ ob,
    int n0,
    const float* __restrict__ bias)
{
    __shared__ __align__(16) unsigned As[16*SA];
    __shared__ __align__(16) unsigned Bs[16*SA];

    int tid  = threadIdx.x;
    int lane = tid & 31, warp = tid >> 5;
    int wm = warp >> 1, wn = warp & 1;
    int gid = lane >> 2, tig = lane & 3;

    float acc[2][8][4];
    #pragma unroll
    for (int mt = 0; mt < 2; mt++)
        #pragma unroll
        for (int nt = 0; nt < 8; nt++)
            #pragma unroll
            for (int i = 0; i < 4; i++) acc[mt][nt][i] = 0.f;

    int arow = tid >> 1,  akq = (tid & 1) * 8;
    int brow = tid >> 4,  bnq = (tid & 15) * 8;

    for (int k0 = 0; k0 < CC; k0 += 16) {
        float4 a0 = *(const float4*)(wb + (size_t)arow*CC + k0 + akq);
        float4 a1 = *(const float4*)(wb + (size_t)arow*CC + k0 + akq + 4);
        float4 b0 = *(const float4*)(xb + (size_t)(k0 + brow)*HW + n0 + bnq);
        float4 b1 = *(const float4*)(xb + (size_t)(k0 + brow)*HW + n0 + bnq + 4);
        __syncthreads();
        As[(akq+0)*SA + arow] = f2tf(a0.x);
        As[(akq+1)*SA + arow] = f2tf(a0.y);
        As[(akq+2)*SA + arow] = f2tf(a0.z);
        As[(akq+3)*SA + arow] = f2tf(a0.w);
        As[(akq+4)*SA + arow] = f2tf(a1.x);
        As[(akq+5)*SA + arow] = f2tf(a1.y);
        As[(akq+6)*SA + arow] = f2tf(a1.z);
        As[(akq+7)*SA + arow] = f2tf(a1.w);
        *(uint4*)&Bs[brow*SA + bnq]     = make_uint4(f2tf(b0.x), f2tf(b0.y), f2tf(b0.z), f2tf(b0.w));
        *(uint4*)&Bs[brow*SA + bnq + 4] = make_uint4(f2tf(b1.x), f2tf(b1.y), f2tf(b1.z), f2tf(b1.w));
        __syncthreads();

        #pragma unroll
        for (int kk = 0; kk < 16; kk += 8) {
            unsigned af[2][4], bf[8][2];
            #pragma unroll
            for (int mt = 0; mt < 2; mt++) {
                int m = wm*32 + mt*16 + gid;
                af[mt][0] = As[(kk+tig  )*SA + m];
                af[mt][1] = As[(kk+tig  )*SA + m + 8];
                af[mt][2] = As[(kk+tig+4)*SA + m];
                af[mt][3] = As[(kk+tig+4)*SA + m + 8];
            }
            #pragma unroll
            for (int nt = 0; nt < 8; nt++) {
                int n = wn*64 + nt*8 + gid;
                bf[nt][0] = Bs[(kk+tig  )*SA + n];
                bf[nt][1] = Bs[(kk+tig+4)*SA + n];
            }
            #pragma unroll
            for (int mt = 0; mt < 2; mt++)
                #pragma unroll
                for (int nt = 0; nt < 8; nt++)
                    mma8(acc[mt][nt], af[mt], bf[nt]);
        }
    }

    #pragma unroll
    for (int mt = 0; mt < 2; mt++) {
        int r0 = wm*32 + mt*16 + gid;
        float bia0 = bias ? bias[r0]     : 0.f;
        float bia1 = bias ? bias[r0 + 8] : 0.f;
        #pragma unroll
        for (int nt = 0; nt < 8; nt++) {
            int c = n0 + wn*64 + nt*8 + 2*tig;
            *(float2*)(ob + (size_t)r0*HW + c) =
                make_float2(acc[mt][nt][0] + bia0, acc[mt][nt][1] + bia0);
            *(float2*)(ob + (size_t)(r0+8)*HW + c) =
                make_float2(acc[mt][nt][2] + bia1, acc[mt][nt][3] + bia1);
        }
    }
}

// ---------------- qkv GEMM (tf32 tensor cores) ----------------
__global__ void __launch_bounds__(256) qkv_gemm(const float* __restrict__ X,
                                                const float* __restrict__ Wq,
                                                int which)
{
    int b  = blockIdx.z;
    int by = blockIdx.y;
    int n0 = blockIdx.x * 128;
    float* outA = which ? g_k  : g_q;
    float* outB = which ? g_v2 : g_v1;
    int wrowA   = which ? 256 : 0;
    const float* wb;
    float* ob;
    if (by < 2) { wb = Wq + (size_t)(wrowA + by*128)*CC;
                  ob = outA + (size_t)b*CC*HW + (size_t)(by*128)*HW; }
    else        { wb = Wq + (size_t)(512 + (by-2)*128)*CC;
                  ob = outB + (size_t)b*CC*HW + (size_t)((by-2)*128)*HW; }
    const float* xb = X + (size_t)b*CC*HW;
    gemm128_tf32(wb, xb, ob, n0, nullptr);
}

// ---------------- pointwise GEMM (BN folded, tf32) ----------------
__global__ void __launch_bounds__(256) pw_gemm(float* __restrict__ out)
{
    int b  = blockIdx.z;
    int by = blockIdx.y;
    int n0 = blockIdx.x * 128;
    const float* wb = g_pwf + (size_t)(by*128)*CC;
    const float* xb = g_u + (size_t)b*CC*HW;
    float* ob = out + (size_t)b*CC*HW + (size_t)(by*128)*HW;
    gemm128_tf32(wb, xb, ob, n0, g_pwb + by*128);
}

// ---------------- window attention: tensor-core (mma tf32) ----------------
// o = 0.5*( softmax(q k^T * 0.25 + bias) @ (v1-v2) + sum_k v2 )
// block = 1 window x 2 heads, 4 warps; warp owns 32 queries of one head.
// smem layout: d-major, token stride 72 (conflict-free fragment reads & stores)
#define TS 72
#define HSZ (16*TS)

__global__ void __launch_bounds__(128) attn_kernel()
{
    int wid = blockIdx.x;                 // 0..2047
    int hp  = blockIdx.y;                 // head pair 0..7
    int b   = wid >> 10;
    int wy  = (wid >> 5) & 31;
    int wx  = wid & 31;
    int tid = threadIdx.x;
    int lane = tid & 31, warp = tid >> 5;
    int hh    = warp >> 1;                // head within pair
    int mbase = (warp & 1) * 32;          // query base
    int g = lane >> 2, t = lane & 3;

    __shared__ float sq [2*HSZ];          // [head][d][token], q * 0.25*log2e
    __shared__ float sk [2*HSZ];
    __shared__ float svd[2*HSZ];          // 0.5*(v1-v2)
    __shared__ float svs[2*16];           // 0.5*sum_k v2

    if (tid < 32) svs[tid] = 0.f;
    __syncthreads();

    // load window tiles
    for (int e = tid; e < 2048; e += 128) {
        int lh = e >> 10;
        int r  = e & 1023;
        int dd = r >> 6, tk = r & 63;
        size_t ga = ((size_t)b*CC + (hp*2+lh)*DHH + dd)*HW
                  + (size_t)(wy*8 + (tk>>3))*WIMG + wx*8 + (tk&7);
        sq[lh*HSZ + dd*TS + tk] = g_q[ga] * QSCALE;
        sk[lh*HSZ + dd*TS + tk] = g_k[ga];
        float v1 = g_v1[ga], v2 = g_v2[ga];
        svd[lh*HSZ + dd*TS + tk] = 0.5f*(v1 - v2);
        float s = 0.5f*v2;                 // all 32 lanes share (lh,dd)
        #pragma unroll
        for (int o = 16; o > 0; o >>= 1) s += __shfl_xor_sync(0xffffffffu, s, o);
        if (lane == 0) atomicAdd(&svs[lh*16 + dd], s);
    }
    __syncthreads();

    const float* qh = sq  + hh*HSZ;
    const float* kh = sk  + hh*HSZ;
    const float* vh = svd + hh*HSZ;
    int hgl = hp*2 + hh;

    // Q A-fragments (M=32: 2 m-tiles, K=16: 2 k-chunks)
    unsigned aq[2][2][4];
    #pragma unroll
    for (int mi = 0; mi < 2; mi++) {
        int r0 = mbase + mi*16 + g;
        #pragma unroll
        for (int kc = 0; kc < 2; kc++) {
            aq[mi][kc][0] = f2tf(qh[(kc*8+t  )*TS + r0]);
            aq[mi][kc][1] = f2tf(qh[(kc*8+t  )*TS + r0+8]);
            aq[mi][kc][2] = f2tf(qh[(kc*8+t+4)*TS + r0]);
            aq[mi][kc][3] = f2tf(qh[(kc*8+t+4)*TS + r0+8]);
        }
    }

    // S accumulators initialized with bias fragments (already x log2e)
    float acc[2][8][4];
    #pragma unroll
    for (int mi = 0; mi < 2; mi++) {
        int mtg = (warp & 1)*2 + mi;
        #pragma unroll
        for (int ni = 0; ni < 8; ni++) {
            float4 bv = *(const float4*)&g_biasf[(((hgl*4 + mtg)*8 + ni)*128 + lane*4)];
            acc[mi][ni][0] = bv.x; acc[mi][ni][1] = bv.y;
            acc[mi][ni][2] = bv.z; acc[mi][ni][3] = bv.w;
        }
    }

    // S = (0.25*log2e)*Q K^T + log2e*bias
    #pragma unroll
    for (int ni = 0; ni < 8; ni++) {
        unsigned bk[2][2];
        #pragma unroll
        for (int kc = 0; kc < 2; kc++) {
            bk[kc][0] = f2tf(kh[(kc*8+t  )*TS + ni*8 + g]);
            bk[kc][1] = f2tf(kh[(kc*8+t+4)*TS + ni*8 + g]);
        }
        #pragma unroll
        for (int mi = 0; mi < 2; mi++)
            #pragma unroll
            for (int kc = 0; kc < 2; kc++)
                mma8(acc[mi][ni], aq[mi][kc], bk[kc]);
    }

    // softmax (base-2) per row; rows g (regs 0,1) and g+8 (regs 2,3)
    #pragma unroll
    for (int mi = 0; mi < 2; mi++) {
        float m0 = -1e30f, m1 = -1e30f;
        #pragma unroll
        for (int ni = 0; ni < 8; ni++) {
            m0 = fmaxf(m0, fmaxf(acc[mi][ni][0], acc[mi][ni][1]));
            m1 = fmaxf(m1, fmaxf(acc[mi][ni][2], acc[mi][ni][3]));
        }
        m0 = fmaxf(m0, __shfl_xor_sync(0xffffffffu, m0, 1));
        m0 = fmaxf(m0, __shfl_xor_sync(0xffffffffu, m0, 2));
        m1 = fmaxf(m1, __shfl_xor_sync(0xffffffffu, m1, 1));
        m1 = fmaxf(m1, __shfl_xor_sync(0xffffffffu, m1, 2));
        float s0 = 0.f, s1 = 0.f;
        #pragma unroll
        for (int ni = 0; ni < 8; ni++) {
            float p0 = ex2(acc[mi][ni][0] - m0);
            float p1 = ex2(acc[mi][ni][1] - m0);
            float p2 = ex2(acc[mi][ni][2] - m1);
            float p3 = ex2(acc[mi][ni][3] - m1);
            acc[mi][ni][0] = p0; acc[mi][ni][1] = p1;
            acc[mi][ni][2] = p2; acc[mi][ni][3] = p3;
            s0 += p0 + p1; s1 += p2 + p3;
        }
        s0 += __shfl_xor_sync(0xffffffffu, s0, 1);
        s0 += __shfl_xor_sync(0xffffffffu, s0, 2);
        s1 += __shfl_xor_sync(0xffffffffu, s1, 1);
        s1 += __shfl_xor_sync(0xffffffffu, s1, 2);
        float i0 = 1.0f / s0, i1 = 1.0f / s1;
        // normalize and convert to tf32 bits in place
        #pragma unroll
        for (int ni = 0; ni < 8; ni++) {
            acc[mi][ni][0] = __uint_as_float(f2tf(acc[mi][ni][0]*i0));
            acc[mi][ni][1] = __uint_as_float(f2tf(acc[mi][ni][1]*i0));
            acc[mi][ni][2] = __uint_as_float(f2tf(acc[mi][ni][2]*i1));
            acc[mi][ni][3] = __uint_as_float(f2tf(acc[mi][ni][3]*i1));
        }
    }

    // AV accumulators initialized with 0.5*sum_k v2 (cols = d)
    float av[2][2][4];
    #pragma unroll
    for (int mi = 0; mi < 2; mi++)
        #pragma unroll
        for (int no = 0; no < 2; no++) {
            float c0 = svs[hh*16 + no*8 + 2*t];
            float c1 = svs[hh*16 + no*8 + 2*t + 1];
            av[mi][no][0] = c0; av[mi][no][1] = c1;
            av[mi][no][2] = c0; av[mi][no][3] = c1;
        }

    // AV: P @ (0.5*(v1-v2)); P C-layout -> A-layout via quad shuffles
    int src0 = (g << 2) | (t >> 1);
    int src1 = src0 + 2;
    bool odd = (t & 1);
    #pragma unroll
    for (int kc2 = 0; kc2 < 8; kc2++) {
        unsigned pa[2][4];
        #pragma unroll
        for (int mi = 0; mi < 2; mi++) {
            float r0 = acc[mi][kc2][0], r1 = acc[mi][kc2][1];
            float r2 = acc[mi][kc2][2], r3 = acc[mi][kc2][3];
            float x00 = __shfl_sync(0xffffffffu, r0, src0);
            float x01 = __shfl_sync(0xffffffffu, r1, src0);
            float x02 = __shfl_sync(0xffffffffu, r2, src0);
            float x03 = __shfl_sync(0xffffffffu, r3, src0);
            float x10 = __shfl_sync(0xffffffffu, r0, src1);
            float x11 = __shfl_sync(0xffffffffu, r1, src1);
            float x12 = __shfl_sync(0xffffffffu, r2, src1);
            float x13 = __shfl_sync(0xffffffffu, r3, src1);
            pa[mi][0] = __float_as_uint(odd ? x01 : x00);
            pa[mi][1] = __float_as_uint(odd ? x03 : x02);
            pa[mi][2] = __float_as_uint(odd ? x11 : x10);
            pa[mi][3] = __float_as_uint(odd ? x13 : x12);
        }
        unsigned bv[2][2];
        #pragma unroll
        for (int no = 0; no < 2; no++) {
            bv[no][0] = f2tf(vh[(no*8+g)*TS + kc2*8 + t]);
            bv[no][1] = f2tf(vh[(no*8+g)*TS + kc2*8 + t + 4]);
        }
        #pragma unroll
        for (int mi = 0; mi < 2; mi++)
            #pragma unroll
            for (int no = 0; no < 2; no++)
                mma8(av[mi][no], pa[mi], bv[no]);
    }

    // write out (0.5 factors already folded)
    size_t hb = ((size_t)b*CC + hgl*DHH)*HW + (size_t)(wy*8)*WIMG + wx*8;
    #pragma unroll
    for (int mi = 0; mi < 2; mi++) {
        int r0 = mbase + mi*16 + g;
        int r1 = r0 + 8;
        #pragma unroll
        for (int no = 0; no < 2; no++) {
            int d0 = no*8 + 2*t;
            g_o[hb + (size_t)(d0  )*HW + (r0>>3)*WIMG + (r0&7)] = av[mi][no][0];
            g_o[hb + (size_t)(d0+1)*HW + (r0>>3)*WIMG + (r0&7)] = av[mi][no][1];
            g_o[hb + (size_t)(d0  )*HW + (r1>>3)*WIMG + (r1&7)] = av[mi][no][2];
            g_o[hb + (size_t)(d0+1)*HW + (r1>>3)*WIMG + (r1&7)] = av[mi][no][3];
        }
    }
}

// ---------------- directional avg pools + pad_out ----------------
__global__ void pool_kernel()
{
    int p = blockIdx.x*256 + threadIdx.x;
    if (p >= TPL) return;
    int c = blockIdx.y, b = blockIdx.z;
    int y = p / TP, x = p - y*TP;
    const float* ob = g_o + ((size_t)b*CC + c)*HW;
    float val = 0.f;
    if (y < 256 && x < 256) {
        float sx = 0.f, sy = 0.f;
        #pragma unroll
        for (int t = 0; t < 8; t++) {
            int r = y - 3 + t;
            if (r >= 0 && r <= 256) sx += ob[(r == 256 ? 254 : r)*WIMG + x];
            int cl = x - 3 + t;
            if (cl >= 0 && cl <= 256) sy += ob[y*WIMG + (cl == 256 ? 254 : cl)];
        }
        val = (sx + sy)*0.125f;
    }
    g_t[((size_t)b*CC + c)*TPL + p] = val;
}

// ---------------- depthwise 8x8 conv (pad 3) over t[257x257] -> u[256x256] ----
__global__ void __launch_bounds__(256) dw_kernel(const float* __restrict__ dw)
{
    __shared__ float st[39][41];
    __shared__ float sdw[64];
    int bc = blockIdx.z;
    int y0 = blockIdx.y*32, x0 = blockIdx.x*32;
    const float* tb = g_t + (size_t)bc*TPL;
    int tid = threadIdx.x;
    if (tid < 64) sdw[tid] = dw[(bc & 255)*64 + tid];
    for (int idx = tid; idx < 39*39; idx += 256) {
        int r = idx / 39, cl = idx - r*39;
        int gy = y0 - 3 + r, gx = x0 - 3 + cl;
        float v = 0.f;
        if (gy >= 0 && gy < TP && gx >= 0 && gx < TP) v = tb[gy*TP + gx];
        st[r][cl] = v;
    }
    __syncthreads();
    int oy = tid >> 3, ox = (tid & 7)*4;
    float a0 = 0.f, a1 = 0.f, a2 = 0.f, a3 = 0.f;
    #pragma unroll
    for (int ky = 0; ky < 8; ky++) {
        const float* row = &st[oy+ky][ox];
        #pragma unroll
        for (int kx = 0; kx < 8; kx++) {
            float wv = sdw[ky*8 + kx];
            a0 += wv*row[kx];
            a1 += wv*row[kx+1];
            a2 += wv*row[kx+2];
            a3 += wv*row[kx+3];
        }
    }
    float* up = g_u + (size_t)bc*HW + (size_t)(y0+oy)*WIMG + x0 + ox;
    *(float4*)up = make_float4(a0,a1,a2,a3);
}

// ---------------- launch ----------------
extern "C" void kernel_launch(void* const* d_in, const int* in_sizes, int n_in,
                              void* d_out, int out_size)
{
    const float* x1       = (const float*)d_in[0];
    const float* x2       = (const float*)d_in[1];
    const float* qkv_w    = (const float*)d_in[2];
    const float* rel_bias = (const float*)d_in[3];
    const float* dw_w     = (const float*)d_in[4];
    const float* bn_g     = (const float*)d_in[5];
    const float* bn_b     = (const float*)d_in[6];
    const float* bn_m     = (const float*)d_in[7];
    const float* bn_v     = (const float*)d_in[8];
    const float* pw_w     = (const float*)d_in[9];
    float* out = (float*)d_out;

    prep_kernel<<<256, 256>>>(pw_w, bn_g, bn_b, bn_m, bn_v);
    bias_prep<<<dim3(NHH, 4, 8), 32>>>(rel_bias);
    qkv_gemm<<<dim3(512, 4, BB), 256>>>(x1, qkv_w, 0);
    qkv_gemm<<<dim3(512, 4, BB), 256>>>(x2, qkv_w, 1);
    attn_kernel<<<dim3(2048, 8), 128>>>();
    pool_kernel<<<dim3((TPL + 255)/256, CC, BB), 256>>>();
    dw_kernel<<<dim3(8, 8, BB*CC), 256>>>(dw_w);
    pw_gemm<<<dim3(512, 2, BB), 256>>>(out);
}